// round 7
// baseline (speedup 1.0000x reference)
#include <cuda_runtime.h>
#include <cuda_bf16.h>
#include <cstdint>

// Shape: masks [16,512,1024,4] f32, src_stft [16,512,2048,4] f32.
// loss = mean |masks - onehot(argmax_C src_stft[:,:,:1024,:])|
//
// Identity (masks in [0,1)):  sum_c |m_c - onehot_c| = (sum_c m_c) + 1 - 2*m_{argmax}
// -> accumulate (sum_m - 2*m_sel) per group, add NG once at the end.
//
// Blocked layout: BT = 16*512 = 8192 rows; each row is 1024 float4 groups
// (16 KB) in masks and the first 1024 of 2048 groups in stft. 2048 blocks
// each own exactly 4 rows -> all loads are 16 KB sequential runs, no
// div/mod address math, no tail.

static constexpr int   BT       = 16 * 512;             // 8192 rows
static constexpr int   FG       = 1024;                 // float4 groups per row
static constexpr int   NG       = BT * FG;              // 8,388,608
static constexpr int   THREADS  = 256;
static constexpr int   BLOCKS   = 2048;
static constexpr int   ROWS_PB  = BT / BLOCKS;          // 4 rows per block, exact
static constexpr int   ITERS    = FG / THREADS;         // 4 passes per row, exact
static constexpr float INV_N    = 1.0f / 33554432.0f;   // 1 / 2^25 (exact)

__device__ float        g_partial;  // zero at module load; reset by last block
__device__ unsigned int g_count;

__global__ __launch_bounds__(THREADS) void recon_loss_kernel(
    const float4* __restrict__ masks,
    const float4* __restrict__ stft,
    float* __restrict__ out)
{
    float acc = 0.0f;

    #pragma unroll 1
    for (int r = 0; r < ROWS_PB; r++) {
        const int bt = blockIdx.x + r * BLOCKS;
        const float4* __restrict__ mrow = masks + (size_t)bt * FG;
        const float4* __restrict__ grow = stft  + (size_t)bt * (2 * FG);

        #pragma unroll
        for (int k = 0; k < ITERS; k++) {
            const int f = threadIdx.x + k * THREADS;
            const float4 g = __ldg(&grow[f]);
            const float4 m = __ldg(&mrow[f]);

            // first-max argmax over C=4 (strict > keeps earliest index),
            // carrying the matching mask component.
            float best = g.x, msel = m.x;
            if (g.y > best) { best = g.y; msel = m.y; }
            if (g.z > best) { best = g.z; msel = m.z; }
            if (g.w > best) { best = g.w; msel = m.w; }

            acc += (m.x + m.y) + (m.z + m.w) - 2.0f * msel;
        }
    }

    // warp reduce
    #pragma unroll
    for (int off = 16; off > 0; off >>= 1)
        acc += __shfl_xor_sync(0xFFFFFFFFu, acc, off);

    __shared__ float warp_sums[THREADS / 32];
    const int lane = threadIdx.x & 31;
    const int wid  = threadIdx.x >> 5;
    if (lane == 0) warp_sums[wid] = acc;
    __syncthreads();

    if (wid == 0) {
        float s = (lane < THREADS / 32) ? warp_sums[lane] : 0.0f;
        #pragma unroll
        for (int off = 4; off > 0; off >>= 1)
            s += __shfl_xor_sync(0xFFFFFFFFu, s, off);

        if (lane == 0) {
            atomicAdd(&g_partial, s);
            __threadfence();
            const unsigned done = atomicAdd(&g_count, 1u);
            if (done == (unsigned)gridDim.x - 1u) {
                // Last block: read-and-reset so graph replays stay deterministic.
                const float total = atomicExch(&g_partial, 0.0f);
                atomicExch(&g_count, 0u);
                out[0] = (total + (float)NG) * INV_N;  // +NG = "+1 per group"
            }
        }
    }
}

extern "C" void kernel_launch(void* const* d_in, const int* in_sizes, int n_in,
                              void* d_out, int out_size)
{
    const float4* masks = (const float4*)d_in[0];
    const float4* stft  = (const float4*)d_in[1];
    float* out = (float*)d_out;

    recon_loss_kernel<<<BLOCKS, THREADS>>>(masks, stft, out);
}